// round 3
// baseline (speedup 1.0000x reference)
#include <cuda_runtime.h>
#include <cstdint>

#define T_STEPS 128
#define B_SZ    128
#define N_RES   4096
#define IN_DIM  1024
#define MAX_DIM 4608
#define M_A     (T_STEPS * B_SZ)   // 16384 rows for phase A

// ---------------- scratch (device globals; no cudaMalloc allowed) ----------
__device__ float g_P[(size_t)M_A * N_RES];         // input_part, 268 MB
__device__ float g_G[(size_t)M_A * 3 * N_RES];     // gates (post-sigmoid), 805 MB
__device__ float g_state[B_SZ * N_RES];            // recurrent state, 2 MB
__device__ float g_part[4][B_SZ * N_RES];          // K-split partials, 8 MB

// ---------------- small helpers -------------------------------------------
__device__ __forceinline__ uint32_t cvt_tf32(float x) {
    uint32_t r;
    asm("cvt.rna.tf32.f32 %0, %1;" : "=r"(r) : "f"(x));
    return r;
}

__device__ __forceinline__ void mma_tf32_16x8x8(float* d, const uint32_t* a, const uint32_t* b) {
    asm volatile(
        "mma.sync.aligned.m16n8k8.row.col.f32.tf32.tf32.f32 "
        "{%0,%1,%2,%3}, {%4,%5,%6,%7}, {%8,%9}, {%0,%1,%2,%3};"
        : "+f"(d[0]), "+f"(d[1]), "+f"(d[2]), "+f"(d[3])
        : "r"(a[0]), "r"(a[1]), "r"(a[2]), "r"(a[3]), "r"(b[0]), "r"(b[1]));
}

__device__ __forceinline__ void cp16(void* sm, const void* gm) {
    uint32_t s = (uint32_t)__cvta_generic_to_shared(sm);
    asm volatile("cp.async.cg.shared.global [%0], [%1], 16;" :: "r"(s), "l"(gm));
}
#define CP_COMMIT() asm volatile("cp.async.commit_group;")
#define CP_WAIT1()  asm volatile("cp.async.wait_group 1;")

// ===========================================================================
// Phase A: C[m,f] = sum_k X[m,k] * W[f,k]   (M=16384, F=16384, K=1024)
// f < 4096  -> g_P (raw);  f >= 4096 -> g_G (sigmoid applied)
// CTA tile 128x128, 8 warps (2x4), warp tile 64x32, KC=16, double-buffered.
// ===========================================================================
__global__ __launch_bounds__(256) void phaseA_gemm(const float* __restrict__ X,
                                                   const float* __restrict__ W_in,
                                                   const float* __restrict__ W_gate) {
    __shared__ float As[2][128][20];   // [m][k], stride 20 words (80B, 16B aligned, bank-clean)
    __shared__ float Bs[2][128][20];   // [f][k]

    const int tid  = threadIdx.x;
    const int warp = tid >> 5, lane = tid & 31;
    const int g  = lane >> 2, tg = lane & 3;
    const int wm = warp >> 2, wn = warp & 3;            // 2 x 4 warp grid
    const int mbase = blockIdx.y * 128;
    const int fblk  = blockIdx.x;                       // 0..127
    const bool isP  = (fblk < 32);
    const float* W  = isP ? W_in : W_gate;
    const int frow0 = isP ? fblk * 128 : (fblk - 32) * 128;

    float acc[4][4][4];
    #pragma unroll
    for (int i = 0; i < 4; i++)
        #pragma unroll
        for (int j = 0; j < 4; j++)
            #pragma unroll
            for (int c = 0; c < 4; c++) acc[i][j][c] = 0.f;

    const int NIT = IN_DIM / 16;   // 64

    auto load_stage = [&](int s, int it) {
        const int k0 = it * 16;
        #pragma unroll
        for (int r = 0; r < 2; r++) {
            int c = tid + r * 256;
            int row = c >> 2, seg = c & 3;
            cp16(&As[s][row][seg * 4], X + (size_t)(mbase + row) * IN_DIM + k0 + seg * 4);
        }
        #pragma unroll
        for (int r = 0; r < 2; r++) {
            int c = tid + r * 256;
            int row = c >> 2, seg = c & 3;
            cp16(&Bs[s][row][seg * 4], W + (size_t)(frow0 + row) * IN_DIM + k0 + seg * 4);
        }
    };

    load_stage(0, 0);
    CP_COMMIT();

    for (int it = 0; it < NIT; it++) {
        const int s = it & 1;
        if (it + 1 < NIT) load_stage(s ^ 1, it + 1);
        CP_COMMIT();
        CP_WAIT1();
        __syncthreads();

        #pragma unroll
        for (int kk = 0; kk < 16; kk += 8) {
            uint32_t af[4][4], bf[4][2];
            #pragma unroll
            for (int mt = 0; mt < 4; mt++) {
                const int r = wm * 64 + mt * 16 + g;
                af[mt][0] = cvt_tf32(As[s][r    ][kk + tg    ]);
                af[mt][1] = cvt_tf32(As[s][r + 8][kk + tg    ]);
                af[mt][2] = cvt_tf32(As[s][r    ][kk + tg + 4]);
                af[mt][3] = cvt_tf32(As[s][r + 8][kk + tg + 4]);
            }
            #pragma unroll
            for (int nt = 0; nt < 4; nt++) {
                const int fc = wn * 32 + nt * 8 + g;
                bf[nt][0] = cvt_tf32(Bs[s][fc][kk + tg    ]);
                bf[nt][1] = cvt_tf32(Bs[s][fc][kk + tg + 4]);
            }
            #pragma unroll
            for (int mt = 0; mt < 4; mt++)
                #pragma unroll
                for (int nt = 0; nt < 4; nt++)
                    mma_tf32_16x8x8(acc[mt][nt], af[mt], bf[nt]);
        }
        __syncthreads();
    }

    // epilogue
    #pragma unroll
    for (int mt = 0; mt < 4; mt++) {
        #pragma unroll
        for (int nt = 0; nt < 4; nt++) {
            const int fc = fblk * 128 + wn * 32 + nt * 8 + 2 * tg;   // global feature col
            #pragma unroll
            for (int half = 0; half < 2; half++) {
                const int m = mbase + wm * 64 + mt * 16 + g + half * 8;
                const float v0 = acc[mt][nt][half * 2 + 0];
                const float v1 = acc[mt][nt][half * 2 + 1];
                if (isP) {
                    *(float2*)&g_P[(size_t)m * N_RES + fc] = make_float2(v0, v1);
                } else {
                    float2 o = make_float2(1.f / (1.f + __expf(-v0)),
                                           1.f / (1.f + __expf(-v1)));
                    *(float2*)&g_G[(size_t)m * (3 * N_RES) + (fc - N_RES)] = o;
                }
            }
        }
    }
}

// ===========================================================================
// Phase B per-step GEMM: R[m,n] = sum_k state[m,k] * W_res[k,n]
// grid = (32 n-tiles, 4 k-splits); CTA tile 128x128, K-chunk = 1024 per split.
// Writes partial sums to g_part[ks].
// ===========================================================================
__global__ __launch_bounds__(256) void stepB_gemm(const float* __restrict__ Wres) {
    __shared__ float As[2][128][20];    // state rows [m][k]
    __shared__ float Bs[2][16][136];    // W_res tile [k][n], stride 136 words (bank-clean)

    const int tid  = threadIdx.x;
    const int warp = tid >> 5, lane = tid & 31;
    const int g  = lane >> 2, tg = lane & 3;
    const int wm = warp >> 2, wn = warp & 3;
    const int nbase  = blockIdx.x * 128;
    const int kbase0 = blockIdx.y * 1024;

    float acc[4][4][4];
    #pragma unroll
    for (int i = 0; i < 4; i++)
        #pragma unroll
        for (int j = 0; j < 4; j++)
            #pragma unroll
            for (int c = 0; c < 4; c++) acc[i][j][c] = 0.f;

    const int NIT = 64;   // 1024 / 16

    auto load_stage = [&](int s, int it) {
        const int k0 = kbase0 + it * 16;
        #pragma unroll
        for (int r = 0; r < 2; r++) {
            int c = tid + r * 256;
            int row = c >> 2, seg = c & 3;
            cp16(&As[s][row][seg * 4], g_state + (size_t)row * N_RES + k0 + seg * 4);
        }
        #pragma unroll
        for (int r = 0; r < 2; r++) {
            int c = tid + r * 256;
            int kr = c >> 5, seg = c & 31;
            cp16(&Bs[s][kr][seg * 4], Wres + (size_t)(k0 + kr) * N_RES + nbase + seg * 4);
        }
    };

    load_stage(0, 0);
    CP_COMMIT();

    for (int it = 0; it < NIT; it++) {
        const int s = it & 1;
        if (it + 1 < NIT) load_stage(s ^ 1, it + 1);
        CP_COMMIT();
        CP_WAIT1();
        __syncthreads();

        #pragma unroll
        for (int kk = 0; kk < 16; kk += 8) {
            uint32_t af[4][4], bf[4][2];
            #pragma unroll
            for (int mt = 0; mt < 4; mt++) {
                const int r = wm * 64 + mt * 16 + g;
                af[mt][0] = cvt_tf32(As[s][r    ][kk + tg    ]);
                af[mt][1] = cvt_tf32(As[s][r + 8][kk + tg    ]);
                af[mt][2] = cvt_tf32(As[s][r    ][kk + tg + 4]);
                af[mt][3] = cvt_tf32(As[s][r + 8][kk + tg + 4]);
            }
            #pragma unroll
            for (int nt = 0; nt < 4; nt++) {
                const int col = wn * 32 + nt * 8 + g;
                bf[nt][0] = cvt_tf32(Bs[s][kk + tg    ][col]);
                bf[nt][1] = cvt_tf32(Bs[s][kk + tg + 4][col]);
            }
            #pragma unroll
            for (int mt = 0; mt < 4; mt++)
                #pragma unroll
                for (int nt = 0; nt < 4; nt++)
                    mma_tf32_16x8x8(acc[mt][nt], af[mt], bf[nt]);
        }
        __syncthreads();
    }

    float* part = g_part[blockIdx.y];
    #pragma unroll
    for (int mt = 0; mt < 4; mt++) {
        #pragma unroll
        for (int nt = 0; nt < 4; nt++) {
            const int n = nbase + wn * 32 + nt * 8 + 2 * tg;
            #pragma unroll
            for (int half = 0; half < 2; half++) {
                const int m = wm * 64 + mt * 16 + g + half * 8;
                *(float2*)&part[(size_t)m * N_RES + n] =
                    make_float2(acc[mt][nt][half * 2 + 0], acc[mt][nt][half * 2 + 1]);
            }
        }
    }
}

// ===========================================================================
// Per-step reduce + cell update + output write (deterministic, no atomics)
// ===========================================================================
__global__ __launch_bounds__(256) void update_kernel(float* __restrict__ out, int t) {
    const int n = blockIdx.x * 256 + threadIdx.x;   // 0..4095
    const int b = blockIdx.y;
    const int idx = b * N_RES + n;

    const float res = g_part[0][idx] + g_part[1][idx] + g_part[2][idx] + g_part[3][idx];
    const float prev = g_state[idx];

    const size_t mrow = (size_t)t * B_SZ + b;
    const float pp = g_P[mrow * N_RES + n];
    const float* gr = g_G + mrow * (3 * N_RES);
    const float gi = gr[n];
    const float gf = gr[N_RES + n];
    const float go = gr[2 * N_RES + n];

    const float z = gi * (pp + res);
    float s = 0.9f * gf * prev + 0.1f * tanhf(z);
    s *= go;
    if (s > 0.5f) s -= 0.5f;

    g_state[idx] = s;
    out[mrow * MAX_DIM + n] = s;
}

// ---------------- init / padding ------------------------------------------
__global__ __launch_bounds__(256) void init_state_kernel(const float* __restrict__ state0) {
    const int n = blockIdx.x * 256 + threadIdx.x;
    const int b = blockIdx.y;
    g_state[b * N_RES + n] = state0[(size_t)b * MAX_DIM + n];
}

__global__ __launch_bounds__(256) void pad_out_kernel(float* __restrict__ out) {
    const size_t idx = (size_t)blockIdx.x * 256 + threadIdx.x;   // over T*B*512
    const size_t tb = idx >> 9;
    const int c = (int)(idx & 511);
    out[tb * MAX_DIM + N_RES + c] = 0.f;
}

// ===========================================================================
extern "C" void kernel_launch(void* const* d_in, const int* in_sizes, int n_in,
                              void* d_out, int out_size) {
    const float* x      = (const float*)d_in[0];   // [T,B,1024]
    const float* state0 = (const float*)d_in[1];   // [B,4608]
    const float* W_res  = (const float*)d_in[2];   // [4096,4096]
    const float* W_in   = (const float*)d_in[3];   // [4096,1024]
    const float* W_gate = (const float*)d_in[4];   // [12288,1024]
    float* out = (float*)d_out;                    // [T,B,4608]

    init_state_kernel<<<dim3(16, 128), 256>>>(state0);
    pad_out_kernel<<<32768, 256>>>(out);

    // Phase A: all input-dependent terms in one big GEMM
    phaseA_gemm<<<dim3(128, 128), 256>>>(x, W_in, W_gate);

    // Phase B: sequential recurrence
    for (int t = 0; t < T_STEPS; t++) {
        stepB_gemm<<<dim3(32, 4), 256>>>(W_res);
        update_kernel<<<dim3(16, 128), 256>>>(out, t);
    }
}